// round 8
// baseline (speedup 1.0000x reference)
#include <cuda_runtime.h>
#include <cuda_bf16.h>

// AdderConvReLUBlock: out = relu(-Σ_{ci,ky,kx} |xp - w|).
// Every accumulated term |patch - w| >= 0, so the pre-ReLU value is <= 0
// everywhere and relu() maps it to exactly 0. The reference output is
// identically zero; the job reduces to an 8 MB zero-fill of d_out.
//
// R1: STG.128 kernel            8.58 µs total
// R2: fat 512-block kernel      8.93 µs (launch ramp dominates)
// R3: single graph memset node  6.50 µs  <-- best
// R4: TWO parallel memset nodes via capture fork/join — halves device-side
//     fill time if one memset node doesn't already saturate the fill path.
//
// Side stream + fork/join events are created at static-init time (before the
// harness's memory baseline), never inside kernel_launch. No device memory is
// allocated anywhere by this file.

namespace {
struct SideStream {
    cudaStream_t s2 = nullptr;
    cudaEvent_t  fork = nullptr;
    cudaEvent_t  join = nullptr;
    bool ok = false;
    SideStream() {
        ok = (cudaStreamCreateWithFlags(&s2, cudaStreamNonBlocking) == cudaSuccess)
          && (cudaEventCreateWithFlags(&fork, cudaEventDisableTiming) == cudaSuccess)
          && (cudaEventCreateWithFlags(&join, cudaEventDisableTiming) == cudaSuccess);
    }
};
SideStream g_side;  // constructed before main(), part of the harness baseline
}  // namespace

extern "C" void kernel_launch(void* const* d_in, const int* in_sizes, int n_in,
                              void* d_out, int out_size) {
    (void)d_in; (void)in_sizes; (void)n_in;

    size_t total = (size_t)out_size * sizeof(float);

    if (g_side.ok) {
        size_t half = total >> 1;
        char* p = (char*)d_out;
        // Fork: side stream joins the capture via the fork event.
        cudaEventRecord(g_side.fork, 0);
        cudaStreamWaitEvent(g_side.s2, g_side.fork, 0);
        // Two independent memset nodes — execute concurrently in the graph.
        cudaMemsetAsync(p,        0, half,         0);
        cudaMemsetAsync(p + half, 0, total - half, g_side.s2);
        // Join: capture stream waits for the side branch.
        cudaEventRecord(g_side.join, g_side.s2);
        cudaStreamWaitEvent(0, g_side.join, 0);
    } else {
        // Fallback: single memset node (the proven 6.5 µs path).
        cudaMemsetAsync(d_out, 0, total, 0);
    }
}

// round 11
// speedup vs baseline: 1.3558x; 1.3558x over previous
#include <cuda_runtime.h>
#include <cuda_bf16.h>

// AdderConvReLUBlock: out = relu(-Σ_{ci,ky,kx} |xp - w|).
// Every accumulated term |patch - w| is >= 0, so the pre-ReLU value is
// -Σ|·| <= 0 at every output element, and relu() maps it to exactly 0.
// The reference output is identically the zero tensor — the entire adder-conv
// is algebraically dead under the ReLU. The optimal implementation is a pure
// 8 MB zero-fill of d_out.
//
// Measured history (total dur_us, graph-replay timing):
//   R1: 2048-block STG.128 kernel        8.58 µs
//   R2: 512-block fat kernel             8.93 µs (launch ramp dominates)
//   R3: single graph memset node         6.50 µs  <-- floor
//   R4: two parallel memset nodes        9.02 µs (per-node replay cost >> fill)
//
// Conclusion: replay overhead is per-node; the minimum-cost graph is exactly
// one memset node. This is R3, final.

extern "C" void kernel_launch(void* const* d_in, const int* in_sizes, int n_in,
                              void* d_out, int out_size) {
    (void)d_in; (void)in_sizes; (void)n_in;
    // Graph-capturable: becomes a single native memset node. No allocation,
    // no sync, deterministic.
    cudaMemsetAsync(d_out, 0, (size_t)out_size * sizeof(float), 0);
}